// round 5
// baseline (speedup 1.0000x reference)
#include <cuda_runtime.h>
#include <cstdint>
#include <math.h>

#define B_  8192
#define H_  512
#define G3_ 1536
#define V_  2048
#define T_  24

// ---------------------------------------------------------------------------
// Scratch (device globals: allocation-free)
// ---------------------------------------------------------------------------
__device__ float g_h[B_ * H_];        // hidden state
__device__ float g_inp[B_ * H_];      // step input
__device__ float g_gi[B_ * G3_];      // inp @ W_ih^T + b_ih
__device__ float g_gh[B_ * G3_];      // h   @ W_hh^T + b_hh
__device__ float g_logits[B_ * V_];   // h   @ W_out^T + b_out

// ---------------------------------------------------------------------------
// Threefry-2x32 (exact JAX replica)
// ---------------------------------------------------------------------------
__host__ __device__ __forceinline__ uint32_t rotl32(uint32_t v, int r) {
    return (v << r) | (v >> (32 - r));
}

__host__ __device__ __forceinline__ void tf2x32(uint32_t k0, uint32_t k1,
                                                uint32_t c0, uint32_t c1,
                                                uint32_t &o0, uint32_t &o1) {
    const uint32_t k2 = k0 ^ k1 ^ 0x1BD11BDAu;
    uint32_t a = c0, b = c1;
    a += k0; b += k1;
#define TFR(r) { a += b; b = rotl32(b, r); b ^= a; }
    TFR(13) TFR(15) TFR(26) TFR(6)
    a += k1; b += k2 + 1u;
    TFR(17) TFR(29) TFR(16) TFR(24)
    a += k2; b += k0 + 2u;
    TFR(13) TFR(15) TFR(26) TFR(6)
    a += k0; b += k1 + 3u;
    TFR(17) TFR(29) TFR(16) TFR(24)
    a += k1; b += k2 + 4u;
    TFR(13) TFR(15) TFR(26) TFR(6)
    a += k2; b += k0 + 5u;
#undef TFR
    o0 = a; o1 = b;
}

// gumbel = -log(-log(u)), u per JAX: max(tiny, bitcast((bits>>9)|1.0f) - 1)
__device__ __forceinline__ float gumbelf(uint32_t bits) {
    float f = __uint_as_float((bits >> 9) | 0x3F800000u) - 1.0f;
    float u = fmaxf(1.17549435082228751e-38f, f);
    return -logf(-logf(u));
}

// XLA logistic: 0.5 + 0.5*tanh(0.5*x)
__device__ __forceinline__ float sigx(float v) {
    return 0.5f * tanhf(0.5f * v) + 0.5f;
}

// ---------------------------------------------------------------------------
// GEMM: C[M,N] = A[M,512] * B[N,512]^T + bias[N]  (row-major, K = 512)
// 128x128 tile, 256 threads, 8x8 micro-tile, BK=8, double-buffered smem.
// M = 8192, N in {1536, 2048}: all dims divide tiles -> no bounds checks.
// ---------------------------------------------------------------------------
__global__ void __launch_bounds__(256) gemm512(const float *__restrict__ A,
                                               const float *__restrict__ Bm,
                                               const float *__restrict__ bias,
                                               float *__restrict__ C, int N) {
    __shared__ float As[2][8][128];
    __shared__ float Bs[2][8][128];

    const int tid = threadIdx.x;
    const int m0 = blockIdx.y << 7;
    const int n0 = blockIdx.x << 7;

    const int lr = tid >> 1;            // 0..127
    const int lk = (tid & 1) << 2;      // 0 or 4

    const float *Ap = A + (size_t)(m0 + lr) * 512 + lk;
    const float *Bp = Bm + (size_t)(n0 + lr) * 512 + lk;

    float4 ra = *(const float4 *)Ap;
    float4 rb = *(const float4 *)Bp;
    As[0][lk + 0][lr] = ra.x; As[0][lk + 1][lr] = ra.y;
    As[0][lk + 2][lr] = ra.z; As[0][lk + 3][lr] = ra.w;
    Bs[0][lk + 0][lr] = rb.x; Bs[0][lk + 1][lr] = rb.y;
    Bs[0][lk + 2][lr] = rb.z; Bs[0][lk + 3][lr] = rb.w;
    __syncthreads();

    const int tx = (tid & 15) << 3;
    const int ty = (tid >> 4) << 3;

    float acc[8][8];
#pragma unroll
    for (int i = 0; i < 8; i++)
#pragma unroll
        for (int j = 0; j < 8; j++) acc[i][j] = 0.0f;

#pragma unroll 1
    for (int kt = 0; kt < 64; ++kt) {
        const int buf = kt & 1;
        if (kt < 63) {
            ra = *(const float4 *)(Ap + (kt + 1) * 8);
            rb = *(const float4 *)(Bp + (kt + 1) * 8);
        }
#pragma unroll
        for (int k = 0; k < 8; ++k) {
            float av[8], bv[8];
            *(float4 *)(av)     = *(const float4 *)(&As[buf][k][ty]);
            *(float4 *)(av + 4) = *(const float4 *)(&As[buf][k][ty + 4]);
            *(float4 *)(bv)     = *(const float4 *)(&Bs[buf][k][tx]);
            *(float4 *)(bv + 4) = *(const float4 *)(&Bs[buf][k][tx + 4]);
#pragma unroll
            for (int i = 0; i < 8; i++)
#pragma unroll
                for (int j = 0; j < 8; j++)
                    acc[i][j] = fmaf(av[i], bv[j], acc[i][j]);
        }
        if (kt < 63) {
            const int nb = buf ^ 1;
            As[nb][lk + 0][lr] = ra.x; As[nb][lk + 1][lr] = ra.y;
            As[nb][lk + 2][lr] = ra.z; As[nb][lk + 3][lr] = ra.w;
            Bs[nb][lk + 0][lr] = rb.x; Bs[nb][lk + 1][lr] = rb.y;
            Bs[nb][lk + 2][lr] = rb.z; Bs[nb][lk + 3][lr] = rb.w;
            __syncthreads();
        }
    }

    float bb[8];
#pragma unroll
    for (int j = 0; j < 8; j++) bb[j] = bias[n0 + tx + j];
#pragma unroll
    for (int i = 0; i < 8; i++) {
        float4 o0, o1;
        o0.x = acc[i][0] + bb[0]; o0.y = acc[i][1] + bb[1];
        o0.z = acc[i][2] + bb[2]; o0.w = acc[i][3] + bb[3];
        o1.x = acc[i][4] + bb[4]; o1.y = acc[i][5] + bb[5];
        o1.z = acc[i][6] + bb[6]; o1.w = acc[i][7] + bb[7];
        float *cp = C + (size_t)(m0 + ty + i) * N + n0 + tx;
        *(float4 *)(cp)     = o0;
        *(float4 *)(cp + 4) = o1;
    }
}

// ---------------------------------------------------------------------------
// GRU cell + LayerNorm. One block per batch row, 512 threads (one per unit).
// In-place update of g_h.
// ---------------------------------------------------------------------------
__global__ void __launch_bounds__(512) gru_ln(const float *__restrict__ ln_g,
                                              const float *__restrict__ ln_b) {
    const int b = blockIdx.x;
    const int j = threadIdx.x;
    __shared__ float red[512];

    const float *gib = g_gi + (size_t)b * G3_;
    const float *ghb = g_gh + (size_t)b * G3_;
    float hv = g_h[(size_t)b * H_ + j];

    float r = sigx(gib[j] + ghb[j]);
    float z = sigx(gib[512 + j] + ghb[512 + j]);
    float n = tanhf(gib[1024 + j] + r * ghb[1024 + j]);
    float hn = (1.0f - z) * n + z * hv;

    red[j] = hn; __syncthreads();
    for (int s = 256; s > 0; s >>= 1) {
        if (j < s) red[j] += red[j + s];
        __syncthreads();
    }
    float mu = red[0] * (1.0f / 512.0f);
    __syncthreads();

    float d = hn - mu;
    red[j] = d * d; __syncthreads();
    for (int s = 256; s > 0; s >>= 1) {
        if (j < s) red[j] += red[j + s];
        __syncthreads();
    }
    float var = red[0] * (1.0f / 512.0f);

    g_h[(size_t)b * H_ + j] = d * rsqrtf(var + 1e-5f) * ln_g[j] + ln_b[j];
}

// ---------------------------------------------------------------------------
// log_softmax + Gumbel argmax + entropy + embedding gather.
// PARTITIONABLE threefry (modern JAX default): per-element counter
//   (hi, lo) = (0, flat_index), bits = o0 ^ o1.
// One block per batch row, 256 threads x 8 vocab columns each.
// ---------------------------------------------------------------------------
__global__ void __launch_bounds__(256) sample_k(
    const float *__restrict__ etab, uint32_t k0, uint32_t k1, int t,
    float *__restrict__ oSeq, float *__restrict__ oLp, float *__restrict__ oEnt) {
    const int b = blockIdx.x;        // 0..8191
    const int tid = threadIdx.x;

    float xx[8], gg[8];
    const float *L = g_logits + (size_t)b * V_;
#pragma unroll
    for (int i = 0; i < 8; i++) {
        int v = tid + i * 256;
        xx[i] = L[v];
        uint32_t j = (uint32_t)b * 2048u + (uint32_t)v;   // flat index < 2^24
        uint32_t o0, o1;
        tf2x32(k0, k1, 0u, j, o0, o1);                    // counter = (hi=0, lo=j)
        gg[i] = gumbelf(o0 ^ o1);
    }

    __shared__ float red[256];
    __shared__ float redv[256];
    __shared__ float redl[256];
    __shared__ int   redi[256];

    // max
    float m = -INFINITY;
#pragma unroll
    for (int i = 0; i < 8; i++) m = fmaxf(m, xx[i]);
    red[tid] = m; __syncthreads();
    for (int s = 128; s > 0; s >>= 1) {
        if (tid < s) red[tid] = fmaxf(red[tid], red[tid + s]);
        __syncthreads();
    }
    m = red[0]; __syncthreads();

    // sum exp(x - m)
    float ss = 0.0f;
#pragma unroll
    for (int i = 0; i < 8; i++) ss += expf(xx[i] - m);
    red[tid] = ss; __syncthreads();
    for (int s = 128; s > 0; s >>= 1) {
        if (tid < s) red[tid] += red[tid + s];
        __syncthreads();
    }
    float Lg = logf(red[0]); __syncthreads();

    // per-element: lsm, entropy, gumbel argmax (first-index tie-break)
    float bv = -INFINITY, blsm = 0.0f, ent = 0.0f;
    int bi = 0x7FFFFFFF;
#pragma unroll
    for (int i = 0; i < 8; i++) {
        int v = tid + i * 256;
        float lsm = (xx[i] - m) - Lg;
        ent += expf(lsm) * lsm;
        float val = lsm + gg[i];
        if (val > bv) { bv = val; bi = v; blsm = lsm; }
    }
    red[tid] = ent; redv[tid] = bv; redi[tid] = bi; redl[tid] = blsm;
    __syncthreads();
    for (int s = 128; s > 0; s >>= 1) {
        if (tid < s) {
            red[tid] += red[tid + s];
            float v2 = redv[tid + s]; int i2 = redi[tid + s];
            if (v2 > redv[tid] || (v2 == redv[tid] && i2 < redi[tid])) {
                redv[tid] = v2; redi[tid] = i2; redl[tid] = redl[tid + s];
            }
        }
        __syncthreads();
    }

    int tok = redi[0];
    if (tid == 0) {
        oSeq[(size_t)b * T_ + t] = (float)tok;
        oLp [(size_t)b * T_ + t] = redl[0];
        oEnt[(size_t)b * T_ + t] = -red[0];
    }

    // embedding gather -> next step input
    for (int c = tid; c < 512; c += 256)
        g_inp[(size_t)b * H_ + c] = etab[(size_t)tok * 512 + c];
}

// ---------------------------------------------------------------------------
// Init: h = embedding, inp = broadcast(sos)
// ---------------------------------------------------------------------------
__global__ void __launch_bounds__(256) init_k(const float *__restrict__ emb,
                                              const float *__restrict__ sos) {
    int i = blockIdx.x * 256 + threadIdx.x;   // < B_*H_
    g_h[i] = emb[i];
    g_inp[i] = sos[i & 511];
}

// ---------------------------------------------------------------------------
// Host launcher (graph-capturable: kernel launches only)
// ---------------------------------------------------------------------------
extern "C" void kernel_launch(void* const* d_in, const int* in_sizes, int n_in,
                              void* d_out, int out_size) {
    (void)in_sizes; (void)n_in; (void)out_size;
    const float* embedding = (const float*)d_in[0];
    /* d_in[1] = max_len (static 24) */
    const float* sos   = (const float*)d_in[2];
    const float* W_ih  = (const float*)d_in[3];
    const float* W_hh  = (const float*)d_in[4];
    const float* b_ih  = (const float*)d_in[5];
    const float* b_hh  = (const float*)d_in[6];
    const float* ln_g  = (const float*)d_in[7];
    const float* ln_b  = (const float*)d_in[8];
    const float* W_out = (const float*)d_in[9];
    const float* b_out = (const float*)d_in[10];
    const float* etab  = (const float*)d_in[11];

    float* out  = (float*)d_out;
    float* oSeq = out;
    float* oLp  = out + (size_t)B_ * T_;
    float* oEnt = out + (size_t)2 * B_ * T_;

    float *ph, *pinp, *pgi, *pgh, *plog;
    cudaGetSymbolAddress((void**)&ph,   g_h);
    cudaGetSymbolAddress((void**)&pinp, g_inp);
    cudaGetSymbolAddress((void**)&pgi,  g_gi);
    cudaGetSymbolAddress((void**)&pgh,  g_gh);
    cudaGetSymbolAddress((void**)&plog, g_logits);

    init_k<<<(B_ * H_) / 256, 256>>>(embedding, sos);

    dim3 gGate(G3_ / 128, B_ / 128);   // 12 x 64
    dim3 gOut (V_  / 128, B_ / 128);   // 16 x 64

    for (int t = 0; t < T_; t++) {
        // folded key: threefry(key=[0,42], count=[0,t])
        uint32_t fk0, fk1;
        tf2x32(0u, 42u, 0u, (uint32_t)t, fk0, fk1);

        gemm512<<<gGate, 256>>>(pinp, W_ih, b_ih, pgi, G3_);
        gemm512<<<gGate, 256>>>(ph,   W_hh, b_hh, pgh, G3_);
        gru_ln<<<B_, 512>>>(ln_g, ln_b);
        gemm512<<<gOut, 256>>>(ph, W_out, b_out, plog, V_);
        sample_k<<<B_, 256>>>(etab, fk0, fk1, t, oSeq, oLp, oEnt);
    }
}

// round 7
// speedup vs baseline: 1.3456x; 1.3456x over previous
#include <cuda_runtime.h>
#include <cuda_bf16.h>
#include <cstdint>
#include <math.h>

#define B_  8192
#define H_  512
#define G3_ 1536
#define V_  2048
#define T_  24

// ---------------------------------------------------------------------------
// Scratch (device globals: allocation-free)
// ---------------------------------------------------------------------------
__device__ float g_h[B_ * H_];        // hidden state (fp32 master)
__device__ float g_gi[B_ * G3_];
__device__ float g_gh[B_ * G3_];
__device__ float g_logits[B_ * V_];

// bf16x3 splits of GEMM operands
__device__ __nv_bfloat16 g_IA0[B_ * H_], g_IA1[B_ * H_], g_IA2[B_ * H_];   // step input
__device__ __nv_bfloat16 g_HA0[B_ * H_], g_HA1[B_ * H_], g_HA2[B_ * H_];   // hidden
__device__ __nv_bfloat16 g_Wih0[G3_ * H_], g_Wih1[G3_ * H_], g_Wih2[G3_ * H_];
__device__ __nv_bfloat16 g_Whh0[G3_ * H_], g_Whh1[G3_ * H_], g_Whh2[G3_ * H_];
__device__ __nv_bfloat16 g_Wo0[V_ * H_],  g_Wo1[V_ * H_],  g_Wo2[V_ * H_];

// ---------------------------------------------------------------------------
// Threefry-2x32 (exact JAX replica)
// ---------------------------------------------------------------------------
__host__ __device__ __forceinline__ uint32_t rotl32(uint32_t v, int r) {
    return (v << r) | (v >> (32 - r));
}

__host__ __device__ __forceinline__ void tf2x32(uint32_t k0, uint32_t k1,
                                                uint32_t c0, uint32_t c1,
                                                uint32_t &o0, uint32_t &o1) {
    const uint32_t k2 = k0 ^ k1 ^ 0x1BD11BDAu;
    uint32_t a = c0, b = c1;
    a += k0; b += k1;
#define TFR(r) { a += b; b = rotl32(b, r); b ^= a; }
    TFR(13) TFR(15) TFR(26) TFR(6)
    a += k1; b += k2 + 1u;
    TFR(17) TFR(29) TFR(16) TFR(24)
    a += k2; b += k0 + 2u;
    TFR(13) TFR(15) TFR(26) TFR(6)
    a += k0; b += k1 + 3u;
    TFR(17) TFR(29) TFR(16) TFR(24)
    a += k1; b += k2 + 4u;
    TFR(13) TFR(15) TFR(26) TFR(6)
    a += k2; b += k0 + 5u;
#undef TFR
    o0 = a; o1 = b;
}

__device__ __forceinline__ float gumbelf(uint32_t bits) {
    float f = __uint_as_float((bits >> 9) | 0x3F800000u) - 1.0f;
    float u = fmaxf(1.17549435082228751e-38f, f);
    return -logf(-logf(u));
}

__device__ __forceinline__ float sigx(float v) {
    return 0.5f * tanhf(0.5f * v) + 0.5f;
}

// split x into 3 bf16 terms (rn at every stage)
__device__ __forceinline__ void split3(float x, __nv_bfloat16 &b0,
                                       __nv_bfloat16 &b1, __nv_bfloat16 &b2) {
    b0 = __float2bfloat16(x);
    float r = x - __bfloat162float(b0);
    b1 = __float2bfloat16(r);
    float r2 = r - __bfloat162float(b1);
    b2 = __float2bfloat16(r2);
}

// ---------------------------------------------------------------------------
// mma.sync / ldmatrix / cp.async primitives (sm_80+, valid on compute_100)
// ---------------------------------------------------------------------------
__device__ __forceinline__ uint32_t smem_u32(const void* p) {
    uint32_t a;
    asm("{ .reg .u64 t; cvta.to.shared.u64 t, %1; cvt.u32.u64 %0, t; }"
        : "=r"(a) : "l"(p));
    return a;
}

__device__ __forceinline__ void ldsm4(uint32_t &r0, uint32_t &r1,
                                      uint32_t &r2, uint32_t &r3, uint32_t addr) {
    asm volatile("ldmatrix.sync.aligned.m8n8.x4.shared.b16 {%0,%1,%2,%3}, [%4];"
                 : "=r"(r0), "=r"(r1), "=r"(r2), "=r"(r3) : "r"(addr));
}

__device__ __forceinline__ void mma16816(float *d, const uint32_t *a,
                                         uint32_t b0, uint32_t b1) {
    asm volatile(
        "mma.sync.aligned.m16n8k16.row.col.f32.bf16.bf16.f32 "
        "{%0,%1,%2,%3},{%4,%5,%6,%7},{%8,%9},{%0,%1,%2,%3};"
        : "+f"(d[0]), "+f"(d[1]), "+f"(d[2]), "+f"(d[3])
        : "r"(a[0]), "r"(a[1]), "r"(a[2]), "r"(a[3]), "r"(b0), "r"(b1));
}

__device__ __forceinline__ void cp16(uint32_t saddr, const void *g) {
    asm volatile("cp.async.cg.shared.global [%0], [%1], 16;"
                 :: "r"(saddr), "l"(g));
}
#define CP_COMMIT() asm volatile("cp.async.commit_group;" ::: "memory")
#define CP_WAIT(n)  asm volatile("cp.async.wait_group %0;" :: "n"(n) : "memory")

// ---------------------------------------------------------------------------
// bf16x3 emulated-fp32 GEMM on HMMA tensor cores:
//   C[M,N] = A[M,512] * W[N,512]^T + bias[N]
// A,W given as 3 bf16 splits each. 128x128 CTA tile, 8 warps (2x4), warp tile
// 64x32. K chunks of 64; per chunk 6 split-pairs (i+j<=2) of m16n8k16 MMAs
// accumulate into one fp32 register tile. 2-stage cp.async pipeline.
// ---------------------------------------------------------------------------
#define TILE_B   16384          // one 128x64 bf16 tile, 128B rows
#define STAGE_B  (6 * TILE_B)   // 96 KB
#define SMEM_TOT (2 * STAGE_B)  // 192 KB

__global__ void __launch_bounds__(256)
gemm_bf3(const __nv_bfloat16 *__restrict__ A0, const __nv_bfloat16 *__restrict__ A1,
         const __nv_bfloat16 *__restrict__ A2, const __nv_bfloat16 *__restrict__ B0,
         const __nv_bfloat16 *__restrict__ B1, const __nv_bfloat16 *__restrict__ B2,
         const float *__restrict__ bias, float *__restrict__ C, int N) {
    extern __shared__ char smem[];
    const uint32_t sb = smem_u32(smem);
    const int tid = threadIdx.x;
    const int wid = tid >> 5;
    const int lane = tid & 31;
    const int m0 = blockIdx.y << 7;
    const int n0 = blockIdx.x << 7;
    const int wm = wid >> 2;            // 0..1 (M)
    const int wn = wid & 3;             // 0..3 (N)

    const __nv_bfloat16 *mats[6] = {
        A0 + (size_t)m0 * 512, A1 + (size_t)m0 * 512, A2 + (size_t)m0 * 512,
        B0 + (size_t)n0 * 512, B1 + (size_t)n0 * 512, B2 + (size_t)n0 * 512};

    // ---- async stage loader: 6 tiles of [128 rows x 64 bf16], swizzled ----
    auto issue = [&](int ch, int buf) {
        const uint32_t bbase = sb + (uint32_t)buf * STAGE_B;
#pragma unroll
        for (int s = 0; s < 24; ++s) {
            int seg = tid + s * 256;          // 0..6143
            int m = seg >> 10;
            int w = seg & 1023;
            int row = w >> 3;
            int u = w & 7;
            uint32_t bo = (uint32_t)(row << 7) + (uint32_t)(u << 4);
            uint32_t sw = bo ^ ((bo >> 3) & 0x70u);
            cp16(bbase + m * TILE_B + sw,
                 mats[m] + (size_t)row * 512 + (ch << 6) + (u << 3));
        }
        CP_COMMIT();
    };

    float acc[4][4][4];
#pragma unroll
    for (int i = 0; i < 4; i++)
#pragma unroll
        for (int j = 0; j < 4; j++)
#pragma unroll
            for (int k = 0; k < 4; k++) acc[i][j][k] = 0.0f;

    issue(0, 0);

#pragma unroll 1
    for (int ch = 0; ch < 8; ++ch) {
        const int buf = ch & 1;
        if (ch < 7) { issue(ch + 1, buf ^ 1); CP_WAIT(1); }
        else        { CP_WAIT(0); }
        __syncthreads();

        const uint32_t stage = sb + (uint32_t)buf * STAGE_B;

#pragma unroll
        for (int ks = 0; ks < 4; ++ks) {
            const uint32_t kb = (uint32_t)(ks * 32) + (uint32_t)((lane >> 4) << 4);
#pragma unroll
            for (int ai = 0; ai < 3; ++ai) {
                // A fragments: 4 m16 tiles
                uint32_t af[4][4];
                const uint32_t At = stage + ai * TILE_B;
#pragma unroll
                for (int mi = 0; mi < 4; ++mi) {
                    uint32_t row = (uint32_t)(wm * 64 + mi * 16 + (lane & 15));
                    uint32_t bo = (row << 7) + kb;
                    uint32_t sw = bo ^ ((bo >> 3) & 0x70u);
                    ldsm4(af[mi][0], af[mi][1], af[mi][2], af[mi][3], At + sw);
                }
#pragma unroll
                for (int bj = 0; bj < 3 - ai; ++bj) {
                    // B fragments: 2 n16 groups (covering n32)
                    uint32_t bq[2][4];
                    const uint32_t Bt = stage + (3 + bj) * TILE_B;
#pragma unroll
                    for (int nh = 0; nh < 2; ++nh) {
                        uint32_t row = (uint32_t)(wn * 32 + nh * 16 + (lane & 15));
                        uint32_t bo = (row << 7) + kb;
                        uint32_t sw = bo ^ ((bo >> 3) & 0x70u);
                        ldsm4(bq[nh][0], bq[nh][1], bq[nh][2], bq[nh][3], Bt + sw);
                    }
#pragma unroll
                    for (int mi = 0; mi < 4; ++mi)
#pragma unroll
                        for (int ni = 0; ni < 4; ++ni)
                            mma16816(acc[mi][ni], af[mi],
                                     bq[ni >> 1][ni & 1], bq[ni >> 1][(ni & 1) + 2]);
                }
            }
        }
        __syncthreads();
    }

    // ---- epilogue: D fragment -> C + bias ----
    const int tr = lane >> 2;           // 0..7
    const int tc = (lane & 3) << 1;     // 0,2,4,6
#pragma unroll
    for (int ni = 0; ni < 4; ++ni) {
        const int col = n0 + wn * 32 + ni * 8 + tc;
        const float bx = bias[col];
        const float by = bias[col + 1];
#pragma unroll
        for (int mi = 0; mi < 4; ++mi) {
            const int r0 = m0 + wm * 64 + mi * 16 + tr;
            float2 v0, v1;
            v0.x = acc[mi][ni][0] + bx; v0.y = acc[mi][ni][1] + by;
            v1.x = acc[mi][ni][2] + bx; v1.y = acc[mi][ni][3] + by;
            *(float2 *)(C + (size_t)r0 * N + col) = v0;
            *(float2 *)(C + (size_t)(r0 + 8) * N + col) = v1;
        }
    }
}

// ---------------------------------------------------------------------------
// GRU cell + LayerNorm; writes fp32 h AND its bf16x3 splits.
// ---------------------------------------------------------------------------
__global__ void __launch_bounds__(512) gru_ln(const float *__restrict__ ln_g,
                                              const float *__restrict__ ln_b) {
    const int b = blockIdx.x;
    const int j = threadIdx.x;
    __shared__ float red[512];

    const float *gib = g_gi + (size_t)b * G3_;
    const float *ghb = g_gh + (size_t)b * G3_;
    float hv = g_h[(size_t)b * H_ + j];

    float r = sigx(gib[j] + ghb[j]);
    float z = sigx(gib[512 + j] + ghb[512 + j]);
    float n = tanhf(gib[1024 + j] + r * ghb[1024 + j]);
    float hn = (1.0f - z) * n + z * hv;

    red[j] = hn; __syncthreads();
    for (int s = 256; s > 0; s >>= 1) {
        if (j < s) red[j] += red[j + s];
        __syncthreads();
    }
    float mu = red[0] * (1.0f / 512.0f);
    __syncthreads();

    float d = hn - mu;
    red[j] = d * d; __syncthreads();
    for (int s = 256; s > 0; s >>= 1) {
        if (j < s) red[j] += red[j + s];
        __syncthreads();
    }
    float var = red[0] * (1.0f / 512.0f);

    float out = d * rsqrtf(var + 1e-5f) * ln_g[j] + ln_b[j];
    size_t idx = (size_t)b * H_ + j;
    g_h[idx] = out;
    __nv_bfloat16 b0, b1, b2;
    split3(out, b0, b1, b2);
    g_HA0[idx] = b0; g_HA1[idx] = b1; g_HA2[idx] = b2;
}

// ---------------------------------------------------------------------------
// log_softmax + Gumbel argmax + entropy + embedding gather (writes IA splits).
// Partitionable threefry: counter (0, flat_index), bits = o0 ^ o1.
// ---------------------------------------------------------------------------
__global__ void __launch_bounds__(256) sample_k(
    const float *__restrict__ etab, uint32_t k0, uint32_t k1, int t,
    float *__restrict__ oSeq, float *__restrict__ oLp, float *__restrict__ oEnt) {
    const int b = blockIdx.x;
    const int tid = threadIdx.x;

    float xx[8], gg[8];
    const float *L = g_logits + (size_t)b * V_;
#pragma unroll
    for (int i = 0; i < 8; i++) {
        int v = tid + i * 256;
        xx[i] = L[v];
        uint32_t j = (uint32_t)b * 2048u + (uint32_t)v;
        uint32_t o0, o1;
        tf2x32(k0, k1, 0u, j, o0, o1);
        gg[i] = gumbelf(o0 ^ o1);
    }

    __shared__ float red[256];
    __shared__ float redv[256];
    __shared__ float redl[256];
    __shared__ int   redi[256];

    float m = -INFINITY;
#pragma unroll
    for (int i = 0; i < 8; i++) m = fmaxf(m, xx[i]);
    red[tid] = m; __syncthreads();
    for (int s = 128; s > 0; s >>= 1) {
        if (tid < s) red[tid] = fmaxf(red[tid], red[tid + s]);
        __syncthreads();
    }
    m = red[0]; __syncthreads();

    float ss = 0.0f;
#pragma unroll
    for (int i = 0; i < 8; i++) ss += expf(xx[i] - m);
    red[tid] = ss; __syncthreads();
    for (int s = 128; s > 0; s >>= 1) {
        if (tid < s) red[tid] += red[tid + s];
        __syncthreads();
    }
    float Lg = logf(red[0]); __syncthreads();

    float bv = -INFINITY, blsm = 0.0f, ent = 0.0f;
    int bi = 0x7FFFFFFF;
#pragma unroll
    for (int i = 0; i < 8; i++) {
        int v = tid + i * 256;
        float lsm = (xx[i] - m) - Lg;
        ent += expf(lsm) * lsm;
        float val = lsm + gg[i];
        if (val > bv) { bv = val; bi = v; blsm = lsm; }
    }
    red[tid] = ent; redv[tid] = bv; redi[tid] = bi; redl[tid] = blsm;
    __syncthreads();
    for (int s = 128; s > 0; s >>= 1) {
        if (tid < s) {
            red[tid] += red[tid + s];
            float v2 = redv[tid + s]; int i2 = redi[tid + s];
            if (v2 > redv[tid] || (v2 == redv[tid] && i2 < redi[tid])) {
                redv[tid] = v2; redi[tid] = i2; redl[tid] = redl[tid + s];
            }
        }
        __syncthreads();
    }

    int tok = redi[0];
    if (tid == 0) {
        oSeq[(size_t)b * T_ + t] = (float)tok;
        oLp [(size_t)b * T_ + t] = redl[0];
        oEnt[(size_t)b * T_ + t] = -red[0];
    }

    for (int c = tid; c < 512; c += 256) {
        float v = etab[(size_t)tok * 512 + c];
        __nv_bfloat16 b0, b1, b2;
        split3(v, b0, b1, b2);
        size_t idx = (size_t)b * H_ + c;
        g_IA0[idx] = b0; g_IA1[idx] = b1; g_IA2[idx] = b2;
    }
}

// ---------------------------------------------------------------------------
// Init: h = embedding (fp32 + splits), inp splits = broadcast(sos)
// ---------------------------------------------------------------------------
__global__ void __launch_bounds__(256) init_k(const float *__restrict__ emb,
                                              const float *__restrict__ sos) {
    int i = blockIdx.x * 256 + threadIdx.x;
    float x = emb[i];
    g_h[i] = x;
    __nv_bfloat16 b0, b1, b2;
    split3(x, b0, b1, b2);
    g_HA0[i] = b0; g_HA1[i] = b1; g_HA2[i] = b2;

    float y = sos[i & 511];
    split3(y, b0, b1, b2);
    g_IA0[i] = b0; g_IA1[i] = b1; g_IA2[i] = b2;
}

// ---------------------------------------------------------------------------
// Weight splitter
// ---------------------------------------------------------------------------
__global__ void __launch_bounds__(256) splitw_k(const float *__restrict__ src,
                                                __nv_bfloat16 *d0, __nv_bfloat16 *d1,
                                                __nv_bfloat16 *d2, int n) {
    int i = blockIdx.x * 256 + threadIdx.x;
    if (i < n) {
        __nv_bfloat16 a, b, c;
        split3(src[i], a, b, c);
        d0[i] = a; d1[i] = b; d2[i] = c;
    }
}

// ---------------------------------------------------------------------------
// Host launcher (graph-capturable)
// ---------------------------------------------------------------------------
extern "C" void kernel_launch(void* const* d_in, const int* in_sizes, int n_in,
                              void* d_out, int out_size) {
    (void)in_sizes; (void)n_in; (void)out_size;
    const float* embedding = (const float*)d_in[0];
    const float* sos   = (const float*)d_in[2];
    const float* W_ih  = (const float*)d_in[3];
    const float* W_hh  = (const float*)d_in[4];
    const float* b_ih  = (const float*)d_in[5];
    const float* b_hh  = (const float*)d_in[6];
    const float* ln_g  = (const float*)d_in[7];
    const float* ln_b  = (const float*)d_in[8];
    const float* W_out = (const float*)d_in[9];
    const float* b_out = (const float*)d_in[10];
    const float* etab  = (const float*)d_in[11];

    float* out  = (float*)d_out;
    float* oSeq = out;
    float* oLp  = out + (size_t)B_ * T_;
    float* oEnt = out + (size_t)2 * B_ * T_;

    cudaFuncSetAttribute(gemm_bf3, cudaFuncAttributeMaxDynamicSharedMemorySize,
                         SMEM_TOT);

    float *pgi, *pgh, *plog;
    cudaGetSymbolAddress((void**)&pgi,  g_gi);
    cudaGetSymbolAddress((void**)&pgh,  g_gh);
    cudaGetSymbolAddress((void**)&plog, g_logits);

    __nv_bfloat16 *ia0, *ia1, *ia2, *ha0, *ha1, *ha2;
    __nv_bfloat16 *wih0, *wih1, *wih2, *whh0, *whh1, *whh2, *wo0, *wo1, *wo2;
    cudaGetSymbolAddress((void**)&ia0, g_IA0); cudaGetSymbolAddress((void**)&ia1, g_IA1);
    cudaGetSymbolAddress((void**)&ia2, g_IA2);
    cudaGetSymbolAddress((void**)&ha0, g_HA0); cudaGetSymbolAddress((void**)&ha1, g_HA1);
    cudaGetSymbolAddress((void**)&ha2, g_HA2);
    cudaGetSymbolAddress((void**)&wih0, g_Wih0); cudaGetSymbolAddress((void**)&wih1, g_Wih1);
    cudaGetSymbolAddress((void**)&wih2, g_Wih2);
    cudaGetSymbolAddress((void**)&whh0, g_Whh0); cudaGetSymbolAddress((void**)&whh1, g_Whh1);
    cudaGetSymbolAddress((void**)&whh2, g_Whh2);
    cudaGetSymbolAddress((void**)&wo0, g_Wo0); cudaGetSymbolAddress((void**)&wo1, g_Wo1);
    cudaGetSymbolAddress((void**)&wo2, g_Wo2);

    // one-time-per-launch weight splits (deterministic, graph-capturable)
    splitw_k<<<(G3_ * H_ + 255) / 256, 256>>>(W_ih,  wih0, wih1, wih2, G3_ * H_);
    splitw_k<<<(G3_ * H_ + 255) / 256, 256>>>(W_hh,  whh0, whh1, whh2, G3_ * H_);
    splitw_k<<<(V_  * H_ + 255) / 256, 256>>>(W_out, wo0,  wo1,  wo2,  V_ * H_);

    init_k<<<(B_ * H_) / 256, 256>>>(embedding, sos);

    dim3 gGate(G3_ / 128, B_ / 128);   // 12 x 64
    dim3 gOut (V_  / 128, B_ / 128);   // 16 x 64

    for (int t = 0; t < T_; t++) {
        uint32_t fk0, fk1;
        tf2x32(0u, 42u, 0u, (uint32_t)t, fk0, fk1);   // fold_in(key(42), t)

        gemm_bf3<<<gGate, 256, SMEM_TOT>>>(ia0, ia1, ia2, wih0, wih1, wih2,
                                           b_ih, pgi, G3_);
        gemm_bf3<<<gGate, 256, SMEM_TOT>>>(ha0, ha1, ha2, whh0, whh1, whh2,
                                           b_hh, pgh, G3_);
        gru_ln<<<B_, 512>>>(ln_g, ln_b);
        gemm_bf3<<<gOut, 256, SMEM_TOT>>>(ha0, ha1, ha2, wo0, wo1, wo2,
                                          b_out, plog, V_);
        sample_k<<<B_, 256>>>(etab, fk0, fk1, t, oSeq, oLp, oEnt);
    }
}

// round 8
// speedup vs baseline: 1.4236x; 1.0579x over previous
#include <cuda_runtime.h>
#include <cuda_bf16.h>
#include <cstdint>
#include <math.h>

#define B_  8192
#define H_  512
#define G3_ 1536
#define V_  2048
#define T_  24

// ---------------------------------------------------------------------------
// Scratch (device globals: allocation-free)
// ---------------------------------------------------------------------------
__device__ float g_h[B_ * H_];        // hidden state (fp32 master)
__device__ float g_gi[B_ * G3_];
__device__ float g_gh[B_ * G3_];
__device__ float g_logits[B_ * V_];

// bf16x3 splits of GEMM operands
__device__ __nv_bfloat16 g_IA0[B_ * H_], g_IA1[B_ * H_], g_IA2[B_ * H_];   // step input
__device__ __nv_bfloat16 g_HA0[B_ * H_], g_HA1[B_ * H_], g_HA2[B_ * H_];   // hidden
__device__ __nv_bfloat16 g_Wih0[G3_ * H_], g_Wih1[G3_ * H_], g_Wih2[G3_ * H_];
__device__ __nv_bfloat16 g_Whh0[G3_ * H_], g_Whh1[G3_ * H_], g_Whh2[G3_ * H_];
__device__ __nv_bfloat16 g_Wo0[V_ * H_],  g_Wo1[V_ * H_],  g_Wo2[V_ * H_];

// ---------------------------------------------------------------------------
// Threefry-2x32 (exact JAX replica)
// ---------------------------------------------------------------------------
__host__ __device__ __forceinline__ uint32_t rotl32(uint32_t v, int r) {
    return (v << r) | (v >> (32 - r));
}

__host__ __device__ __forceinline__ void tf2x32(uint32_t k0, uint32_t k1,
                                                uint32_t c0, uint32_t c1,
                                                uint32_t &o0, uint32_t &o1) {
    const uint32_t k2 = k0 ^ k1 ^ 0x1BD11BDAu;
    uint32_t a = c0, b = c1;
    a += k0; b += k1;
#define TFR(r) { a += b; b = rotl32(b, r); b ^= a; }
    TFR(13) TFR(15) TFR(26) TFR(6)
    a += k1; b += k2 + 1u;
    TFR(17) TFR(29) TFR(16) TFR(24)
    a += k2; b += k0 + 2u;
    TFR(13) TFR(15) TFR(26) TFR(6)
    a += k0; b += k1 + 3u;
    TFR(17) TFR(29) TFR(16) TFR(24)
    a += k1; b += k2 + 4u;
    TFR(13) TFR(15) TFR(26) TFR(6)
    a += k2; b += k0 + 5u;
#undef TFR
    o0 = a; o1 = b;
}

__device__ __forceinline__ float gumbelf(uint32_t bits) {
    float f = __uint_as_float((bits >> 9) | 0x3F800000u) - 1.0f;
    float u = fmaxf(1.17549435082228751e-38f, f);
    return -logf(-logf(u));
}

__device__ __forceinline__ float sigx(float v) {
    return 0.5f * tanhf(0.5f * v) + 0.5f;
}

// split x into 3 bf16 terms (rn at every stage)
__device__ __forceinline__ void split3(float x, __nv_bfloat16 &b0,
                                       __nv_bfloat16 &b1, __nv_bfloat16 &b2) {
    b0 = __float2bfloat16(x);
    float r = x - __bfloat162float(b0);
    b1 = __float2bfloat16(r);
    float r2 = r - __bfloat162float(b1);
    b2 = __float2bfloat16(r2);
}

// ---------------------------------------------------------------------------
// mma.sync / ldmatrix / cp.async primitives (sm_80+, valid on compute_100)
// ---------------------------------------------------------------------------
__device__ __forceinline__ uint32_t smem_u32(const void* p) {
    uint32_t a;
    asm("{ .reg .u64 t; cvta.to.shared.u64 t, %1; cvt.u32.u64 %0, t; }"
        : "=r"(a) : "l"(p));
    return a;
}

__device__ __forceinline__ void ldsm4(uint32_t &r0, uint32_t &r1,
                                      uint32_t &r2, uint32_t &r3, uint32_t addr) {
    asm volatile("ldmatrix.sync.aligned.m8n8.x4.shared.b16 {%0,%1,%2,%3}, [%4];"
                 : "=r"(r0), "=r"(r1), "=r"(r2), "=r"(r3) : "r"(addr));
}

__device__ __forceinline__ void mma16816(float *d, const uint32_t *a,
                                         uint32_t b0, uint32_t b1) {
    asm volatile(
        "mma.sync.aligned.m16n8k16.row.col.f32.bf16.bf16.f32 "
        "{%0,%1,%2,%3},{%4,%5,%6,%7},{%8,%9},{%0,%1,%2,%3};"
        : "+f"(d[0]), "+f"(d[1]), "+f"(d[2]), "+f"(d[3])
        : "r"(a[0]), "r"(a[1]), "r"(a[2]), "r"(a[3]), "r"(b0), "r"(b1));
}

__device__ __forceinline__ void cp16(uint32_t saddr, const void *g) {
    asm volatile("cp.async.cg.shared.global [%0], [%1], 16;"
                 :: "r"(saddr), "l"(g));
}
#define CP_COMMIT() asm volatile("cp.async.commit_group;" ::: "memory")
#define CP_WAIT(n)  asm volatile("cp.async.wait_group %0;" :: "n"(n) : "memory")

// ---------------------------------------------------------------------------
// bf16x3 emulated-fp32 GEMM on HMMA tensor cores:
//   C[M,N] = A[M,512] * W[N,512]^T + bias[N]
// 128x128 CTA tile, 8 warps (2x4), warp tile 64x32.
// K chunks of 32 (64B rows, Swizzle<2,4,3>), 2-stage cp.async pipeline,
// 48KB/stage -> 96KB/CTA -> 2 CTAs/SM.
// Per k16-step: 6 split-pairs (i+j<=2) of m16n8k16 accumulate into fp32 regs.
// If zsel != 0, blockIdx.z picks operand set 0/1 (fused gate GEMMs).
// ---------------------------------------------------------------------------
#define TILE_B   8192           // one 128x32 bf16 tile, 64B rows
#define STAGE_B  (6 * TILE_B)   // 48 KB
#define SMEM_TOT (2 * STAGE_B)  // 96 KB

struct GemmOps { const __nv_bfloat16 *a0, *a1, *a2, *b0, *b1, *b2;
                 const float *bias; float *c; };

__global__ void __launch_bounds__(256, 2)
gemm_bf3(GemmOps op0, GemmOps op1, int N, int use2) {
    extern __shared__ char smem[];
    const uint32_t sb = smem_u32(smem);
    const int tid = threadIdx.x;
    const int wid = tid >> 5;
    const int lane = tid & 31;
    const int m0 = blockIdx.y << 7;
    const int n0 = blockIdx.x << 7;
    const int wm = wid >> 2;            // 0..1 (M)
    const int wn = wid & 3;             // 0..3 (N)

    const GemmOps &op = (use2 && blockIdx.z) ? op1 : op0;
    const __nv_bfloat16 *mats[6] = {
        op.a0 + (size_t)m0 * 512, op.a1 + (size_t)m0 * 512, op.a2 + (size_t)m0 * 512,
        op.b0 + (size_t)n0 * 512, op.b1 + (size_t)n0 * 512, op.b2 + (size_t)n0 * 512};

    // ---- async stage loader: 6 tiles of [128 rows x 32 bf16], swizzled ----
    auto issue = [&](int ch, int buf) {
        const uint32_t bbase = sb + (uint32_t)buf * STAGE_B;
#pragma unroll
        for (int s = 0; s < 12; ++s) {
            int seg = tid + s * 256;          // 0..3071
            int m = seg >> 9;
            int w = seg & 511;
            int row = w >> 2;
            int u = w & 3;
            uint32_t bo = (uint32_t)(row << 6) + (uint32_t)(u << 4);
            uint32_t sw = bo ^ ((bo >> 3) & 0x30u);
            cp16(bbase + m * TILE_B + sw,
                 mats[m] + (size_t)row * 512 + (ch << 5) + (u << 3));
        }
        CP_COMMIT();
    };

    float acc[4][4][4];
#pragma unroll
    for (int i = 0; i < 4; i++)
#pragma unroll
        for (int j = 0; j < 4; j++)
#pragma unroll
            for (int k = 0; k < 4; k++) acc[i][j][k] = 0.0f;

    issue(0, 0);

#pragma unroll 1
    for (int ch = 0; ch < 16; ++ch) {
        const int buf = ch & 1;
        if (ch < 15) { issue(ch + 1, buf ^ 1); CP_WAIT(1); }
        else         { CP_WAIT(0); }
        __syncthreads();

        const uint32_t stage = sb + (uint32_t)buf * STAGE_B;

#pragma unroll
        for (int ks = 0; ks < 2; ++ks) {
            const uint32_t kb = (uint32_t)(ks * 32) + (uint32_t)((lane >> 4) << 4);

            // load all 3 B splits once: 2 n16 groups each
            uint32_t bq[3][2][4];
#pragma unroll
            for (int bj = 0; bj < 3; ++bj) {
                const uint32_t Bt = stage + (3 + bj) * TILE_B;
#pragma unroll
                for (int nh = 0; nh < 2; ++nh) {
                    uint32_t row = (uint32_t)(wn * 32 + nh * 16 + (lane & 15));
                    uint32_t bo = (row << 6) + kb;
                    uint32_t sw = bo ^ ((bo >> 3) & 0x30u);
                    ldsm4(bq[bj][nh][0], bq[bj][nh][1], bq[bj][nh][2], bq[bj][nh][3],
                          Bt + sw);
                }
            }
#pragma unroll
            for (int ai = 0; ai < 3; ++ai) {
                uint32_t af[4][4];
                const uint32_t At = stage + ai * TILE_B;
#pragma unroll
                for (int mi = 0; mi < 4; ++mi) {
                    uint32_t row = (uint32_t)(wm * 64 + mi * 16 + (lane & 15));
                    uint32_t bo = (row << 6) + kb;
                    uint32_t sw = bo ^ ((bo >> 3) & 0x30u);
                    ldsm4(af[mi][0], af[mi][1], af[mi][2], af[mi][3], At + sw);
                }
#pragma unroll
                for (int bj = 0; bj < 3; ++bj) {
                    if (bj >= 3 - ai) break;
#pragma unroll
                    for (int mi = 0; mi < 4; ++mi)
#pragma unroll
                        for (int ni = 0; ni < 4; ++ni)
                            mma16816(acc[mi][ni], af[mi],
                                     bq[bj][ni >> 1][ni & 1], bq[bj][ni >> 1][(ni & 1) + 2]);
                }
            }
        }
        __syncthreads();
    }

    // ---- epilogue: D fragment -> C + bias ----
    const int tr = lane >> 2;           // 0..7
    const int tc = (lane & 3) << 1;     // 0,2,4,6
#pragma unroll
    for (int ni = 0; ni < 4; ++ni) {
        const int col = n0 + wn * 32 + ni * 8 + tc;
        const float bx = op.bias[col];
        const float by = op.bias[col + 1];
#pragma unroll
        for (int mi = 0; mi < 4; ++mi) {
            const int r0 = m0 + wm * 64 + mi * 16 + tr;
            float2 v0, v1;
            v0.x = acc[mi][ni][0] + bx; v0.y = acc[mi][ni][1] + by;
            v1.x = acc[mi][ni][2] + bx; v1.y = acc[mi][ni][3] + by;
            *(float2 *)(op.c + (size_t)r0 * N + col) = v0;
            *(float2 *)(op.c + (size_t)(r0 + 8) * N + col) = v1;
        }
    }
}

// ---------------------------------------------------------------------------
// GRU cell + LayerNorm; writes fp32 h AND its bf16x3 splits.
// Shuffle-based reductions (2 smem rounds instead of 18 syncs).
// ---------------------------------------------------------------------------
__global__ void __launch_bounds__(512) gru_ln(const float *__restrict__ ln_g,
                                              const float *__restrict__ ln_b) {
    const int b = blockIdx.x;
    const int j = threadIdx.x;
    const int wid = j >> 5;
    const int lane = j & 31;
    __shared__ float ws[16];
    __shared__ float bc[2];

    const float *gib = g_gi + (size_t)b * G3_;
    const float *ghb = g_gh + (size_t)b * G3_;
    float hv = g_h[(size_t)b * H_ + j];

    float r = sigx(gib[j] + ghb[j]);
    float z = sigx(gib[512 + j] + ghb[512 + j]);
    float n = tanhf(gib[1024 + j] + r * ghb[1024 + j]);
    float hn = (1.0f - z) * n + z * hv;

    // mean
    float s = hn;
#pragma unroll
    for (int o = 16; o > 0; o >>= 1) s += __shfl_xor_sync(0xFFFFFFFFu, s, o);
    if (lane == 0) ws[wid] = s;
    __syncthreads();
    if (j < 32) {
        float v = (j < 16) ? ws[j] : 0.0f;
#pragma unroll
        for (int o = 8; o > 0; o >>= 1) v += __shfl_xor_sync(0xFFFFFFFFu, v, o);
        if (j == 0) bc[0] = v * (1.0f / 512.0f);
    }
    __syncthreads();
    float mu = bc[0];

    // variance
    float d = hn - mu;
    s = d * d;
#pragma unroll
    for (int o = 16; o > 0; o >>= 1) s += __shfl_xor_sync(0xFFFFFFFFu, s, o);
    if (lane == 0) ws[wid] = s;
    __syncthreads();
    if (j < 32) {
        float v = (j < 16) ? ws[j] : 0.0f;
#pragma unroll
        for (int o = 8; o > 0; o >>= 1) v += __shfl_xor_sync(0xFFFFFFFFu, v, o);
        if (j == 0) bc[1] = v * (1.0f / 512.0f);
    }
    __syncthreads();
    float var = bc[1];

    float out = d * rsqrtf(var + 1e-5f) * ln_g[j] + ln_b[j];
    size_t idx = (size_t)b * H_ + j;
    g_h[idx] = out;
    __nv_bfloat16 b0, b1, b2;
    split3(out, b0, b1, b2);
    g_HA0[idx] = b0; g_HA1[idx] = b1; g_HA2[idx] = b2;
}

// ---------------------------------------------------------------------------
// log_softmax + Gumbel argmax + entropy + embedding gather (writes IA splits).
// Partitionable threefry: counter (0, flat_index), bits = o0 ^ o1.
// ---------------------------------------------------------------------------
__global__ void __launch_bounds__(256) sample_k(
    const float *__restrict__ etab, uint32_t k0, uint32_t k1, int t,
    float *__restrict__ oSeq, float *__restrict__ oLp, float *__restrict__ oEnt) {
    const int b = blockIdx.x;
    const int tid = threadIdx.x;

    float xx[8], gg[8];
    const float *L = g_logits + (size_t)b * V_;
#pragma unroll
    for (int i = 0; i < 8; i++) {
        int v = tid + i * 256;
        xx[i] = L[v];
        uint32_t j = (uint32_t)b * 2048u + (uint32_t)v;
        uint32_t o0, o1;
        tf2x32(k0, k1, 0u, j, o0, o1);
        gg[i] = gumbelf(o0 ^ o1);
    }

    __shared__ float red[256];
    __shared__ float redv[256];
    __shared__ float redl[256];
    __shared__ int   redi[256];

    float m = -INFINITY;
#pragma unroll
    for (int i = 0; i < 8; i++) m = fmaxf(m, xx[i]);
    red[tid] = m; __syncthreads();
    for (int s = 128; s > 0; s >>= 1) {
        if (tid < s) red[tid] = fmaxf(red[tid], red[tid + s]);
        __syncthreads();
    }
    m = red[0]; __syncthreads();

    float ss = 0.0f;
#pragma unroll
    for (int i = 0; i < 8; i++) ss += expf(xx[i] - m);
    red[tid] = ss; __syncthreads();
    for (int s = 128; s > 0; s >>= 1) {
        if (tid < s) red[tid] += red[tid + s];
        __syncthreads();
    }
    float Lg = logf(red[0]); __syncthreads();

    float bv = -INFINITY, blsm = 0.0f, ent = 0.0f;
    int bi = 0x7FFFFFFF;
#pragma unroll
    for (int i = 0; i < 8; i++) {
        int v = tid + i * 256;
        float lsm = (xx[i] - m) - Lg;
        ent += expf(lsm) * lsm;
        float val = lsm + gg[i];
        if (val > bv) { bv = val; bi = v; blsm = lsm; }
    }
    red[tid] = ent; redv[tid] = bv; redi[tid] = bi; redl[tid] = blsm;
    __syncthreads();
    for (int s = 128; s > 0; s >>= 1) {
        if (tid < s) {
            red[tid] += red[tid + s];
            float v2 = redv[tid + s]; int i2 = redi[tid + s];
            if (v2 > redv[tid] || (v2 == redv[tid] && i2 < redi[tid])) {
                redv[tid] = v2; redi[tid] = i2; redl[tid] = redl[tid + s];
            }
        }
        __syncthreads();
    }

    int tok = redi[0];
    if (tid == 0) {
        oSeq[(size_t)b * T_ + t] = (float)tok;
        oLp [(size_t)b * T_ + t] = redl[0];
        oEnt[(size_t)b * T_ + t] = -red[0];
    }

    for (int c = tid; c < 512; c += 256) {
        float v = etab[(size_t)tok * 512 + c];
        __nv_bfloat16 b0, b1, b2;
        split3(v, b0, b1, b2);
        size_t idx = (size_t)b * H_ + c;
        g_IA0[idx] = b0; g_IA1[idx] = b1; g_IA2[idx] = b2;
    }
}

// ---------------------------------------------------------------------------
// Init: h = embedding (fp32 + splits), inp splits = broadcast(sos)
// ---------------------------------------------------------------------------
__global__ void __launch_bounds__(256) init_k(const float *__restrict__ emb,
                                              const float *__restrict__ sos) {
    int i = blockIdx.x * 256 + threadIdx.x;
    float x = emb[i];
    g_h[i] = x;
    __nv_bfloat16 b0, b1, b2;
    split3(x, b0, b1, b2);
    g_HA0[i] = b0; g_HA1[i] = b1; g_HA2[i] = b2;

    float y = sos[i & 511];
    split3(y, b0, b1, b2);
    g_IA0[i] = b0; g_IA1[i] = b1; g_IA2[i] = b2;
}

// ---------------------------------------------------------------------------
// Weight splitter
// ---------------------------------------------------------------------------
__global__ void __launch_bounds__(256) splitw_k(const float *__restrict__ src,
                                                __nv_bfloat16 *d0, __nv_bfloat16 *d1,
                                                __nv_bfloat16 *d2, int n) {
    int i = blockIdx.x * 256 + threadIdx.x;
    if (i < n) {
        __nv_bfloat16 a, b, c;
        split3(src[i], a, b, c);
        d0[i] = a; d1[i] = b; d2[i] = c;
    }
}

// ---------------------------------------------------------------------------
// Host launcher (graph-capturable)
// ---------------------------------------------------------------------------
extern "C" void kernel_launch(void* const* d_in, const int* in_sizes, int n_in,
                              void* d_out, int out_size) {
    (void)in_sizes; (void)n_in; (void)out_size;
    const float* embedding = (const float*)d_in[0];
    const float* sos   = (const float*)d_in[2];
    const float* W_ih  = (const float*)d_in[3];
    const float* W_hh  = (const float*)d_in[4];
    const float* b_ih  = (const float*)d_in[5];
    const float* b_hh  = (const float*)d_in[6];
    const float* ln_g  = (const float*)d_in[7];
    const float* ln_b  = (const float*)d_in[8];
    const float* W_out = (const float*)d_in[9];
    const float* b_out = (const float*)d_in[10];
    const float* etab  = (const float*)d_in[11];

    float* out  = (float*)d_out;
    float* oSeq = out;
    float* oLp  = out + (size_t)B_ * T_;
    float* oEnt = out + (size_t)2 * B_ * T_;

    cudaFuncSetAttribute(gemm_bf3, cudaFuncAttributeMaxDynamicSharedMemorySize,
                         SMEM_TOT);

    float *pgi, *pgh, *plog;
    cudaGetSymbolAddress((void**)&pgi,  g_gi);
    cudaGetSymbolAddress((void**)&pgh,  g_gh);
    cudaGetSymbolAddress((void**)&plog, g_logits);

    __nv_bfloat16 *ia0, *ia1, *ia2, *ha0, *ha1, *ha2;
    __nv_bfloat16 *wih0, *wih1, *wih2, *whh0, *whh1, *whh2, *wo0, *wo1, *wo2;
    cudaGetSymbolAddress((void**)&ia0, g_IA0); cudaGetSymbolAddress((void**)&ia1, g_IA1);
    cudaGetSymbolAddress((void**)&ia2, g_IA2);
    cudaGetSymbolAddress((void**)&ha0, g_HA0); cudaGetSymbolAddress((void**)&ha1, g_HA1);
    cudaGetSymbolAddress((void**)&ha2, g_HA2);
    cudaGetSymbolAddress((void**)&wih0, g_Wih0); cudaGetSymbolAddress((void**)&wih1, g_Wih1);
    cudaGetSymbolAddress((void**)&wih2, g_Wih2);
    cudaGetSymbolAddress((void**)&whh0, g_Whh0); cudaGetSymbolAddress((void**)&whh1, g_Whh1);
    cudaGetSymbolAddress((void**)&whh2, g_Whh2);
    cudaGetSymbolAddress((void**)&wo0, g_Wo0); cudaGetSymbolAddress((void**)&wo1, g_Wo1);
    cudaGetSymbolAddress((void**)&wo2, g_Wo2);

    // one-time-per-launch weight splits (deterministic, graph-capturable)
    splitw_k<<<(G3_ * H_ + 255) / 256, 256>>>(W_ih,  wih0, wih1, wih2, G3_ * H_);
    splitw_k<<<(G3_ * H_ + 255) / 256, 256>>>(W_hh,  whh0, whh1, whh2, G3_ * H_);
    splitw_k<<<(V_  * H_ + 255) / 256, 256>>>(W_out, wo0,  wo1,  wo2,  V_ * H_);

    init_k<<<(B_ * H_) / 256, 256>>>(embedding, sos);

    dim3 gGate(G3_ / 128, B_ / 128, 2);   // 12 x 64 x 2 (fused ih+hh)
    dim3 gOut (V_  / 128, B_ / 128, 1);   // 16 x 64

    GemmOps opIH = {ia0, ia1, ia2, wih0, wih1, wih2, b_ih, pgi};
    GemmOps opHH = {ha0, ha1, ha2, whh0, whh1, whh2, b_hh, pgh};
    GemmOps opO  = {ha0, ha1, ha2, wo0,  wo1,  wo2,  b_out, plog};

    for (int t = 0; t < T_; t++) {
        uint32_t fk0, fk1;
        tf2x32(0u, 42u, 0u, (uint32_t)t, fk0, fk1);   // fold_in(key(42), t)

        gemm_bf3<<<gGate, 256, SMEM_TOT>>>(opIH, opHH, G3_, 1);
        gru_ln<<<B_, 512>>>(ln_g, ln_b);
        gemm_bf3<<<gOut, 256, SMEM_TOT>>>(opO, opO, V_, 0);
        sample_k<<<B_, 256>>>(etab, fk0, fk1, t, oSeq, oLp, oEnt);
    }
}

// round 9
// speedup vs baseline: 2.0913x; 1.4691x over previous
#include <cuda_runtime.h>
#include <cuda_fp16.h>
#include <cstdint>
#include <math.h>

#define B_  8192
#define H_  512
#define G3_ 1536
#define V_  2048
#define T_  24

// residual scale 2^11
#define RSC   2048.0f
#define RSCI  4.8828125e-4f

// ---------------------------------------------------------------------------
// Scratch (device globals: allocation-free)
// ---------------------------------------------------------------------------
__device__ float g_h[B_ * H_];
__device__ float g_gi[B_ * G3_];
__device__ float g_gh[B_ * G3_];
__device__ float g_logits[B_ * V_];

// scaled fp16x2 splits: X = X0 + X1 * 2^-11
__device__ __half g_IA0[B_ * H_],  g_IA1[B_ * H_];
__device__ __half g_HA0[B_ * H_],  g_HA1[B_ * H_];
__device__ __half g_Wih0[G3_ * H_], g_Wih1[G3_ * H_];
__device__ __half g_Whh0[G3_ * H_], g_Whh1[G3_ * H_];
__device__ __half g_Wo0[V_ * H_],   g_Wo1[V_ * H_];

// ---------------------------------------------------------------------------
// Threefry-2x32 (exact JAX replica)
// ---------------------------------------------------------------------------
__host__ __device__ __forceinline__ uint32_t rotl32(uint32_t v, int r) {
    return (v << r) | (v >> (32 - r));
}

__host__ __device__ __forceinline__ void tf2x32(uint32_t k0, uint32_t k1,
                                                uint32_t c0, uint32_t c1,
                                                uint32_t &o0, uint32_t &o1) {
    const uint32_t k2 = k0 ^ k1 ^ 0x1BD11BDAu;
    uint32_t a = c0, b = c1;
    a += k0; b += k1;
#define TFR(r) { a += b; b = rotl32(b, r); b ^= a; }
    TFR(13) TFR(15) TFR(26) TFR(6)
    a += k1; b += k2 + 1u;
    TFR(17) TFR(29) TFR(16) TFR(24)
    a += k2; b += k0 + 2u;
    TFR(13) TFR(15) TFR(26) TFR(6)
    a += k0; b += k1 + 3u;
    TFR(17) TFR(29) TFR(16) TFR(24)
    a += k1; b += k2 + 4u;
    TFR(13) TFR(15) TFR(26) TFR(6)
    a += k2; b += k0 + 5u;
#undef TFR
    o0 = a; o1 = b;
}

__device__ __forceinline__ float gumbelf(uint32_t bits) {
    float f = __uint_as_float((bits >> 9) | 0x3F800000u) - 1.0f;
    float u = fmaxf(1.17549435082228751e-38f, f);
    return -logf(-logf(u));
}

__device__ __forceinline__ float sigx(float v) {
    return 0.5f * tanhf(0.5f * v) + 0.5f;
}

// scaled fp16x2 split: x ≈ h0 + h1 * 2^-11, h1 kept in normal fp16 range
__device__ __forceinline__ void split2(float x, __half &h0, __half &h1) {
    h0 = __float2half_rn(x);
    float r = x - __half2float(h0);
    h1 = __float2half_rn(r * RSC);
}

// ---------------------------------------------------------------------------
// mma.sync / ldmatrix / cp.async primitives (sm_80+, valid on compute_100)
// ---------------------------------------------------------------------------
__device__ __forceinline__ uint32_t smem_u32(const void* p) {
    uint32_t a;
    asm("{ .reg .u64 t; cvta.to.shared.u64 t, %1; cvt.u32.u64 %0, t; }"
        : "=r"(a) : "l"(p));
    return a;
}

__device__ __forceinline__ void ldsm4(uint32_t &r0, uint32_t &r1,
                                      uint32_t &r2, uint32_t &r3, uint32_t addr) {
    asm volatile("ldmatrix.sync.aligned.m8n8.x4.shared.b16 {%0,%1,%2,%3}, [%4];"
                 : "=r"(r0), "=r"(r1), "=r"(r2), "=r"(r3) : "r"(addr));
}

__device__ __forceinline__ void mma16816(float *d, const uint32_t *a,
                                         uint32_t b0, uint32_t b1) {
    asm volatile(
        "mma.sync.aligned.m16n8k16.row.col.f32.f16.f16.f32 "
        "{%0,%1,%2,%3},{%4,%5,%6,%7},{%8,%9},{%0,%1,%2,%3};"
        : "+f"(d[0]), "+f"(d[1]), "+f"(d[2]), "+f"(d[3])
        : "r"(a[0]), "r"(a[1]), "r"(a[2]), "r"(a[3]), "r"(b0), "r"(b1));
}

__device__ __forceinline__ void cp16(uint32_t saddr, const void *g) {
    asm volatile("cp.async.cg.shared.global [%0], [%1], 16;"
                 :: "r"(saddr), "l"(g));
}
#define CP_COMMIT() asm volatile("cp.async.commit_group;" ::: "memory")
#define CP_WAIT(n)  asm volatile("cp.async.wait_group %0;" :: "n"(n) : "memory")

// ---------------------------------------------------------------------------
// scaled-fp16x2 emulated-fp32 GEMM on HMMA:
//   C[M,N] = A[M,512] * W[N,512]^T + bias[N],  A = A0 + A1*2^-11 (fp16 splits)
// CTA tile 128x128, 512 threads = 16 warps (4x4), warp tile 32x32.
// K chunks of 32 (64B rows, Swizzle<2,4,3>), 2-stage cp.async, 32KB/stage.
// 3 HMMA products: A0W0 -> acc_hi; A0W1 + A1W0 -> acc_lo (scale 2^11).
// Epilogue: C = acc_hi + acc_lo*2^-11 + bias.
// ---------------------------------------------------------------------------
#define TILE_B   8192            // 128x32 fp16 tile, 64B rows
#define STAGE_B  (4 * TILE_B)    // 32 KB
#define SMEM_TOT (2 * STAGE_B)   // 64 KB

struct GemmOps { const __half *a0, *a1, *b0, *b1;
                 const float *bias; float *c; };

__global__ void __launch_bounds__(512)
gemm_f16x2(GemmOps op0, GemmOps op1, int N, int use2) {
    extern __shared__ char smem[];
    const uint32_t sb = smem_u32(smem);
    const int tid = threadIdx.x;
    const int wid = tid >> 5;
    const int lane = tid & 31;
    const int m0 = blockIdx.y << 7;
    const int n0 = blockIdx.x << 7;
    const int wm = wid >> 2;            // 0..3 (M)
    const int wn = wid & 3;             // 0..3 (N)

    const GemmOps &op = (use2 && blockIdx.z) ? op1 : op0;
    const __half *mats[4] = {
        op.a0 + (size_t)m0 * 512, op.a1 + (size_t)m0 * 512,
        op.b0 + (size_t)n0 * 512, op.b1 + (size_t)n0 * 512};

    // async stage loader: 4 tiles of [128 rows x 32 fp16], Swizzle<2,4,3>
    auto issue = [&](int ch, int buf) {
        const uint32_t bbase = sb + (uint32_t)buf * STAGE_B;
#pragma unroll
        for (int s = 0; s < 4; ++s) {
            int seg = tid + s * 512;          // 0..2047
            int m = seg >> 9;
            int w = seg & 511;
            int row = w >> 2;
            int u = w & 3;
            uint32_t bo = (uint32_t)(row << 6) + (uint32_t)(u << 4);
            uint32_t sw = bo ^ ((bo >> 3) & 0x30u);
            cp16(bbase + m * TILE_B + sw,
                 mats[m] + (size_t)row * 512 + (ch << 5) + (u << 3));
        }
        CP_COMMIT();
    };

    float hi[2][4][4], lo[2][4][4];
#pragma unroll
    for (int i = 0; i < 2; i++)
#pragma unroll
        for (int j = 0; j < 4; j++)
#pragma unroll
            for (int k = 0; k < 4; k++) { hi[i][j][k] = 0.0f; lo[i][j][k] = 0.0f; }

    issue(0, 0);

#pragma unroll 1
    for (int ch = 0; ch < 16; ++ch) {
        const int buf = ch & 1;
        if (ch < 15) { issue(ch + 1, buf ^ 1); CP_WAIT(1); }
        else         { CP_WAIT(0); }
        __syncthreads();

        const uint32_t stage = sb + (uint32_t)buf * STAGE_B;

#pragma unroll
        for (int ks = 0; ks < 2; ++ks) {
            const uint32_t kb = (uint32_t)(ks * 32) + (uint32_t)((lane >> 4) << 4);

            // B fragments: both splits, 2 n16 groups each
            uint32_t bq[2][2][4];
#pragma unroll
            for (int sp = 0; sp < 2; ++sp) {
                const uint32_t Bt = stage + (2 + sp) * TILE_B;
#pragma unroll
                for (int nh = 0; nh < 2; ++nh) {
                    uint32_t row = (uint32_t)(wn * 32 + nh * 16 + (lane & 15));
                    uint32_t bo = (row << 6) + kb;
                    uint32_t sw = bo ^ ((bo >> 3) & 0x30u);
                    ldsm4(bq[sp][nh][0], bq[sp][nh][1], bq[sp][nh][2], bq[sp][nh][3],
                          Bt + sw);
                }
            }
            // A fragments: both splits, 2 m16 tiles each
            uint32_t af[2][2][4];
#pragma unroll
            for (int sp = 0; sp < 2; ++sp) {
                const uint32_t At = stage + sp * TILE_B;
#pragma unroll
                for (int mi = 0; mi < 2; ++mi) {
                    uint32_t row = (uint32_t)(wm * 32 + mi * 16 + (lane & 15));
                    uint32_t bo = (row << 6) + kb;
                    uint32_t sw = bo ^ ((bo >> 3) & 0x30u);
                    ldsm4(af[sp][mi][0], af[sp][mi][1], af[sp][mi][2], af[sp][mi][3],
                          At + sw);
                }
            }
#pragma unroll
            for (int mi = 0; mi < 2; ++mi)
#pragma unroll
                for (int ni = 0; ni < 4; ++ni) {
                    uint32_t b00 = bq[0][ni >> 1][ni & 1];
                    uint32_t b01 = bq[0][ni >> 1][(ni & 1) + 2];
                    uint32_t b10 = bq[1][ni >> 1][ni & 1];
                    uint32_t b11 = bq[1][ni >> 1][(ni & 1) + 2];
                    mma16816(hi[mi][ni], af[0][mi], b00, b01);   // A0*W0
                    mma16816(lo[mi][ni], af[0][mi], b10, b11);   // A0*W1s
                    mma16816(lo[mi][ni], af[1][mi], b00, b01);   // A1s*W0
                }
        }
        __syncthreads();
    }

    // epilogue: C = hi + lo*2^-11 + bias
    const int tr = lane >> 2;
    const int tc = (lane & 3) << 1;
#pragma unroll
    for (int ni = 0; ni < 4; ++ni) {
        const int col = n0 + wn * 32 + ni * 8 + tc;
        const float bx = op.bias[col];
        const float by = op.bias[col + 1];
#pragma unroll
        for (int mi = 0; mi < 2; ++mi) {
            const int r0 = m0 + wm * 32 + mi * 16 + tr;
            float2 v0, v1;
            v0.x = fmaf(lo[mi][ni][0], RSCI, hi[mi][ni][0]) + bx;
            v0.y = fmaf(lo[mi][ni][1], RSCI, hi[mi][ni][1]) + by;
            v1.x = fmaf(lo[mi][ni][2], RSCI, hi[mi][ni][2]) + bx;
            v1.y = fmaf(lo[mi][ni][3], RSCI, hi[mi][ni][3]) + by;
            *(float2 *)(op.c + (size_t)r0 * N + col) = v0;
            *(float2 *)(op.c + (size_t)(r0 + 8) * N + col) = v1;
        }
    }
}

// ---------------------------------------------------------------------------
// GRU cell + LayerNorm; writes fp32 h AND its fp16x2 splits.
// ---------------------------------------------------------------------------
__global__ void __launch_bounds__(512) gru_ln(const float *__restrict__ ln_g,
                                              const float *__restrict__ ln_b) {
    const int b = blockIdx.x;
    const int j = threadIdx.x;
    const int wid = j >> 5;
    const int lane = j & 31;
    __shared__ float ws[16];
    __shared__ float bc[2];

    const float *gib = g_gi + (size_t)b * G3_;
    const float *ghb = g_gh + (size_t)b * G3_;
    float hv = g_h[(size_t)b * H_ + j];

    float r = sigx(gib[j] + ghb[j]);
    float z = sigx(gib[512 + j] + ghb[512 + j]);
    float n = tanhf(gib[1024 + j] + r * ghb[1024 + j]);
    float hn = (1.0f - z) * n + z * hv;

    float s = hn;
#pragma unroll
    for (int o = 16; o > 0; o >>= 1) s += __shfl_xor_sync(0xFFFFFFFFu, s, o);
    if (lane == 0) ws[wid] = s;
    __syncthreads();
    if (j < 32) {
        float v = (j < 16) ? ws[j] : 0.0f;
#pragma unroll
        for (int o = 8; o > 0; o >>= 1) v += __shfl_xor_sync(0xFFFFFFFFu, v, o);
        if (j == 0) bc[0] = v * (1.0f / 512.0f);
    }
    __syncthreads();
    float mu = bc[0];

    float d = hn - mu;
    s = d * d;
#pragma unroll
    for (int o = 16; o > 0; o >>= 1) s += __shfl_xor_sync(0xFFFFFFFFu, s, o);
    if (lane == 0) ws[wid] = s;
    __syncthreads();
    if (j < 32) {
        float v = (j < 16) ? ws[j] : 0.0f;
#pragma unroll
        for (int o = 8; o > 0; o >>= 1) v += __shfl_xor_sync(0xFFFFFFFFu, v, o);
        if (j == 0) bc[1] = v * (1.0f / 512.0f);
    }
    __syncthreads();
    float var = bc[1];

    float out = d * rsqrtf(var + 1e-5f) * ln_g[j] + ln_b[j];
    size_t idx = (size_t)b * H_ + j;
    g_h[idx] = out;
    __half h0, h1;
    split2(out, h0, h1);
    g_HA0[idx] = h0; g_HA1[idx] = h1;
}

// ---------------------------------------------------------------------------
// log_softmax + Gumbel argmax + entropy + embedding gather (writes IA splits).
// Partitionable threefry: counter (0, flat_index), bits = o0 ^ o1.
// ---------------------------------------------------------------------------
__global__ void __launch_bounds__(256) sample_k(
    const float *__restrict__ etab, uint32_t k0, uint32_t k1, int t,
    float *__restrict__ oSeq, float *__restrict__ oLp, float *__restrict__ oEnt) {
    const int b = blockIdx.x;
    const int tid = threadIdx.x;

    float xx[8], gg[8];
    const float *L = g_logits + (size_t)b * V_;
#pragma unroll
    for (int i = 0; i < 8; i++) {
        int v = tid + i * 256;
        xx[i] = L[v];
        uint32_t j = (uint32_t)b * 2048u + (uint32_t)v;
        uint32_t o0, o1;
        tf2x32(k0, k1, 0u, j, o0, o1);
        gg[i] = gumbelf(o0 ^ o1);
    }

    __shared__ float red[256];
    __shared__ float redv[256];
    __shared__ float redl[256];
    __shared__ int   redi[256];

    float m = -INFINITY;
#pragma unroll
    for (int i = 0; i < 8; i++) m = fmaxf(m, xx[i]);
    red[tid] = m; __syncthreads();
    for (int s = 128; s > 0; s >>= 1) {
        if (tid < s) red[tid] = fmaxf(red[tid], red[tid + s]);
        __syncthreads();
    }
    m = red[0]; __syncthreads();

    float ss = 0.0f;
#pragma unroll
    for (int i = 0; i < 8; i++) ss += expf(xx[i] - m);
    red[tid] = ss; __syncthreads();
    for (int s = 128; s > 0; s >>= 1) {
        if (tid < s) red[tid] += red[tid + s];
        __syncthreads();
    }
    float Lg = logf(red[0]); __syncthreads();

    float bv = -INFINITY, blsm = 0.0f, ent = 0.0f;
    int bi = 0x7FFFFFFF;
#pragma unroll
    for (int i = 0; i < 8; i++) {
        int v = tid + i * 256;
        float lsm = (xx[i] - m) - Lg;
        ent += expf(lsm) * lsm;
        float val = lsm + gg[i];
        if (val > bv) { bv = val; bi = v; blsm = lsm; }
    }
    red[tid] = ent; redv[tid] = bv; redi[tid] = bi; redl[tid] = blsm;
    __syncthreads();
    for (int s = 128; s > 0; s >>= 1) {
        if (tid < s) {
            red[tid] += red[tid + s];
            float v2 = redv[tid + s]; int i2 = redi[tid + s];
            if (v2 > redv[tid] || (v2 == redv[tid] && i2 < redi[tid])) {
                redv[tid] = v2; redi[tid] = i2; redl[tid] = redl[tid + s];
            }
        }
        __syncthreads();
    }

    int tok = redi[0];
    if (tid == 0) {
        oSeq[(size_t)b * T_ + t] = (float)tok;
        oLp [(size_t)b * T_ + t] = redl[0];
        oEnt[(size_t)b * T_ + t] = -red[0];
    }

    for (int c = tid; c < 512; c += 256) {
        float v = etab[(size_t)tok * 512 + c];
        __half h0, h1;
        split2(v, h0, h1);
        size_t idx = (size_t)b * H_ + c;
        g_IA0[idx] = h0; g_IA1[idx] = h1;
    }
}

// ---------------------------------------------------------------------------
// Init: h = embedding (fp32 + splits), inp splits = broadcast(sos)
// ---------------------------------------------------------------------------
__global__ void __launch_bounds__(256) init_k(const float *__restrict__ emb,
                                              const float *__restrict__ sos) {
    int i = blockIdx.x * 256 + threadIdx.x;
    float x = emb[i];
    g_h[i] = x;
    __half h0, h1;
    split2(x, h0, h1);
    g_HA0[i] = h0; g_HA1[i] = h1;

    float y = sos[i & 511];
    split2(y, h0, h1);
    g_IA0[i] = h0; g_IA1[i] = h1;
}

// ---------------------------------------------------------------------------
// Weight splitter
// ---------------------------------------------------------------------------
__global__ void __launch_bounds__(256) splitw_k(const float *__restrict__ src,
                                                __half *d0, __half *d1, int n) {
    int i = blockIdx.x * 256 + threadIdx.x;
    if (i < n) {
        __half a, b;
        split2(src[i], a, b);
        d0[i] = a; d1[i] = b;
    }
}

// ---------------------------------------------------------------------------
// Host launcher (graph-capturable)
// ---------------------------------------------------------------------------
extern "C" void kernel_launch(void* const* d_in, const int* in_sizes, int n_in,
                              void* d_out, int out_size) {
    (void)in_sizes; (void)n_in; (void)out_size;
    const float* embedding = (const float*)d_in[0];
    const float* sos   = (const float*)d_in[2];
    const float* W_ih  = (const float*)d_in[3];
    const float* W_hh  = (const float*)d_in[4];
    const float* b_ih  = (const float*)d_in[5];
    const float* b_hh  = (const float*)d_in[6];
    const float* ln_g  = (const float*)d_in[7];
    const float* ln_b  = (const float*)d_in[8];
    const float* W_out = (const float*)d_in[9];
    const float* b_out = (const float*)d_in[10];
    const float* etab  = (const float*)d_in[11];

    float* out  = (float*)d_out;
    float* oSeq = out;
    float* oLp  = out + (size_t)B_ * T_;
    float* oEnt = out + (size_t)2 * B_ * T_;

    cudaFuncSetAttribute(gemm_f16x2, cudaFuncAttributeMaxDynamicSharedMemorySize,
                         SMEM_TOT);

    float *pgi, *pgh, *plog;
    cudaGetSymbolAddress((void**)&pgi,  g_gi);
    cudaGetSymbolAddress((void**)&pgh,  g_gh);
    cudaGetSymbolAddress((void**)&plog, g_logits);

    __half *ia0, *ia1, *ha0, *ha1;
    __half *wih0, *wih1, *whh0, *whh1, *wo0, *wo1;
    cudaGetSymbolAddress((void**)&ia0, g_IA0); cudaGetSymbolAddress((void**)&ia1, g_IA1);
    cudaGetSymbolAddress((void**)&ha0, g_HA0); cudaGetSymbolAddress((void**)&ha1, g_HA1);
    cudaGetSymbolAddress((void**)&wih0, g_Wih0); cudaGetSymbolAddress((void**)&wih1, g_Wih1);
    cudaGetSymbolAddress((void**)&whh0, g_Whh0); cudaGetSymbolAddress((void**)&whh1, g_Whh1);
    cudaGetSymbolAddress((void**)&wo0, g_Wo0); cudaGetSymbolAddress((void**)&wo1, g_Wo1);

    splitw_k<<<(G3_ * H_ + 255) / 256, 256>>>(W_ih,  wih0, wih1, G3_ * H_);
    splitw_k<<<(G3_ * H_ + 255) / 256, 256>>>(W_hh,  whh0, whh1, G3_ * H_);
    splitw_k<<<(V_  * H_ + 255) / 256, 256>>>(W_out, wo0,  wo1,  V_ * H_);

    init_k<<<(B_ * H_) / 256, 256>>>(embedding, sos);

    dim3 gGate(G3_ / 128, B_ / 128, 2);   // fused ih+hh
    dim3 gOut (V_  / 128, B_ / 128, 1);

    GemmOps opIH = {ia0, ia1, wih0, wih1, b_ih, pgi};
    GemmOps opHH = {ha0, ha1, whh0, whh1, b_hh, pgh};
    GemmOps opO  = {ha0, ha1, wo0,  wo1,  b_out, plog};

    for (int t = 0; t < T_; t++) {
        uint32_t fk0, fk1;
        tf2x32(0u, 42u, 0u, (uint32_t)t, fk0, fk1);   // fold_in(key(42), t)

        gemm_f16x2<<<gGate, 512, SMEM_TOT>>>(opIH, opHH, G3_, 1);
        gru_ln<<<B_, 512>>>(ln_g, ln_b);
        gemm_f16x2<<<gOut, 512, SMEM_TOT>>>(opO, opO, V_, 0);
        sample_k<<<B_, 256>>>(etab, fk0, fk1, t, oSeq, oLp, oEnt);
    }
}